// round 13
// baseline (speedup 1.0000x reference)
#include <cuda_runtime.h>
#include <cuda_bf16.h>
#include <cfloat>
#include <math.h>

// ---------------- problem constants ----------------
#define BB 8
#define NN 2048
#define KK 20
#define PP 64
#define PS 32
#define DD 1024
#define TOK (BB * (PP + 1))   // 520
#define INNER 512
#define MLPD 2048
#define EROWS (BB * NN * KK)  // 327680
#define NPTS (BB * NN)        // 16384

// ---------------- scratch ----------------
__device__ float g_h[NPTS * 512];
__device__ float g_G[BB * NN * NN];
__device__ float g_sq[NPTS];
__device__ int   g_knn[EROWS];
__device__ float g_u[NPTS * 256];
__device__ float g_t2[NPTS * 256];
__device__ float g_umax[NPTS * 256];
__device__ float g_umin[NPTS * 256];
__device__ float g_psum[2048 * 256];
__device__ float g_psq[2048 * 256];
__device__ float g_mean[1024];
__device__ float g_rstd[1024];
__device__ float g_y5[NPTS * DD];
__device__ float g_t[TOK * DD];
__device__ float g_ln[TOK * DD];
__device__ float g_qkv[TOK * 3 * INNER];
__device__ float g_z[TOK * INNER];
__device__ float g_ff[TOK * MLPD];

__device__ __forceinline__ float4 ld4(const float* p) { return *(const float4*)p; }

// ================= double-buffered 128x128x16 SGEMM (gram / conv5 / uv) =================
template <bool TRANSB, int ACT, bool ADDC>
__global__ __launch_bounds__(256, 2)
void gemm128(const float* __restrict__ A, int lda, size_t strideA,
             const float* __restrict__ Bm, int ldb, size_t strideB,
             const float* __restrict__ bias,
             float* __restrict__ C, int ldc, size_t strideC,
             int M, int N, int K)
{
    const int BK = 16;
    __shared__ float As[2][BK][128];
    __shared__ float Bs[2][BK][128];
    A  += (size_t)blockIdx.z * strideA;
    Bm += (size_t)blockIdx.z * strideB;
    C  += (size_t)blockIdx.z * strideC;
    int bm = blockIdx.y * 128, bn = blockIdx.x * 128;
    int tid = threadIdx.x;
    int trow = tid >> 4, tcol = tid & 15;

    float4 ra[2], rb[2];

    auto loadA = [&](int k0) {
#pragma unroll
        for (int i = 0; i < 2; i++) {
            int row = i * 64 + (tid >> 2), q = tid & 3;
            int gm = bm + row, gk = k0 + q * 4;
            if (k0 + BK <= K) {
                ra[i] = (gm < M) ? ld4(&A[(size_t)gm * lda + gk]) : make_float4(0, 0, 0, 0);
            } else {
                float v[4];
#pragma unroll
                for (int j = 0; j < 4; j++)
                    v[j] = (gm < M && gk + j < K) ? A[(size_t)gm * lda + gk + j] : 0.f;
                ra[i] = make_float4(v[0], v[1], v[2], v[3]);
            }
        }
    };
    auto loadB = [&](int k0) {
#pragma unroll
        for (int i = 0; i < 2; i++) {
            if (TRANSB) {
                int row = i * 64 + (tid >> 2), q = tid & 3;
                int gn = bn + row, gk = k0 + q * 4;
                if (k0 + BK <= K) {
                    rb[i] = (gn < N) ? ld4(&Bm[(size_t)gn * ldb + gk]) : make_float4(0, 0, 0, 0);
                } else {
                    float v[4];
#pragma unroll
                    for (int j = 0; j < 4; j++)
                        v[j] = (gn < N && gk + j < K) ? Bm[(size_t)gn * ldb + gk + j] : 0.f;
                    rb[i] = make_float4(v[0], v[1], v[2], v[3]);
                }
            } else {
                int krow = i * 8 + (tid >> 5), nq = tid & 31;
                int gk = k0 + krow, gn = bn + nq * 4;
                if (gk < K && gn < N) rb[i] = ld4(&Bm[(size_t)gk * ldb + gn]);
                else rb[i] = make_float4(0, 0, 0, 0);
            }
        }
    };
    auto storeA = [&](int p) {
#pragma unroll
        for (int i = 0; i < 2; i++) {
            int row = i * 64 + (tid >> 2), q = tid & 3;
            As[p][q * 4 + 0][row] = ra[i].x;
            As[p][q * 4 + 1][row] = ra[i].y;
            As[p][q * 4 + 2][row] = ra[i].z;
            As[p][q * 4 + 3][row] = ra[i].w;
        }
    };
    auto storeB = [&](int p) {
#pragma unroll
        for (int i = 0; i < 2; i++) {
            if (TRANSB) {
                int row = i * 64 + (tid >> 2), q = tid & 3;
                Bs[p][q * 4 + 0][row] = rb[i].x;
                Bs[p][q * 4 + 1][row] = rb[i].y;
                Bs[p][q * 4 + 2][row] = rb[i].z;
                Bs[p][q * 4 + 3][row] = rb[i].w;
            } else {
                int krow = i * 8 + (tid >> 5), nq = tid & 31;
                *(float4*)&Bs[p][krow][nq * 4] = rb[i];
            }
        }
    };

    float acc[8][8];
#pragma unroll
    for (int i = 0; i < 8; i++)
#pragma unroll
        for (int j = 0; j < 8; j++) acc[i][j] = 0.f;

    int nk = (K + BK - 1) / BK;
    loadA(0); loadB(0);
    storeA(0); storeB(0);
    __syncthreads();
    int p = 0;
    for (int it = 0; it < nk; it++) {
        if (it + 1 < nk) { loadA((it + 1) * BK); loadB((it + 1) * BK); }
#pragma unroll
        for (int k = 0; k < BK; k++) {
            float4 a0 = ld4(&As[p][k][trow * 8]);
            float4 a1 = ld4(&As[p][k][trow * 8 + 4]);
            float4 b0 = ld4(&Bs[p][k][tcol * 8]);
            float4 b1 = ld4(&Bs[p][k][tcol * 8 + 4]);
            float a[8] = {a0.x, a0.y, a0.z, a0.w, a1.x, a1.y, a1.z, a1.w};
            float b[8] = {b0.x, b0.y, b0.z, b0.w, b1.x, b1.y, b1.z, b1.w};
#pragma unroll
            for (int i = 0; i < 8; i++)
#pragma unroll
                for (int j = 0; j < 8; j++) acc[i][j] += a[i] * b[j];
        }
        if (it + 1 < nk) { storeA(p ^ 1); storeB(p ^ 1); }
        __syncthreads();
        p ^= 1;
    }
#pragma unroll
    for (int i = 0; i < 8; i++) {
        int gm = bm + trow * 8 + i;
        if (gm >= M) continue;
#pragma unroll
        for (int j = 0; j < 8; j++) {
            int gn = bn + tcol * 8 + j;
            if (gn >= N) continue;
            float v = acc[i][j];
            if (bias) v += bias[gn];
            if (ACT == 1) v = 0.5f * v * (1.f + erff(v * 0.70710678118654752f));
            size_t off = (size_t)gm * ldc + gn;
            if (ADDC) v += C[off];
            C[off] = v;
        }
    }
}

// ================= double-buffered 32x64x32 SGEMM (transformer, B=[K,N]) =================
// 128 threads, TM=TN=4. Small tiles -> many blocks -> good wave packing at M=520.
template <int ACT, bool ADDC>
__global__ __launch_bounds__(128)
void gemm32(const float* __restrict__ A, int lda,
            const float* __restrict__ Bm, int ldb,
            const float* __restrict__ bias,
            float* __restrict__ C, int ldc,
            int M, int N, int K)
{
    const int BK = 32;
    __shared__ float As[2][BK][32];
    __shared__ float Bs[2][BK][64];
    int bm = blockIdx.y * 32, bn = blockIdx.x * 64;
    int tid = threadIdx.x;
    int trow = tid >> 4, tcol = tid & 15;   // 8 x 16
    float4 ra[2], rb[4];

    auto loadA = [&](int k0) {
        int row = tid >> 2, q = tid & 3;    // 32 rows, 4 quarters
        int gm = bm + row, gk = k0 + q * 8;
        if (gm < M) {
            ra[0] = ld4(&A[(size_t)gm * lda + gk]);
            ra[1] = ld4(&A[(size_t)gm * lda + gk + 4]);
        } else {
            ra[0] = make_float4(0, 0, 0, 0);
            ra[1] = make_float4(0, 0, 0, 0);
        }
    };
    auto loadB = [&](int k0) {
        int krow = tid >> 2, n0 = bn + (tid & 3) * 16;
        int gk = k0 + krow;
#pragma unroll
        for (int i = 0; i < 4; i++)
            rb[i] = ld4(&Bm[(size_t)gk * ldb + n0 + i * 4]);
    };
    auto storeA = [&](int p) {
        int row = tid >> 2, q = tid & 3;
#pragma unroll
        for (int i = 0; i < 2; i++) {
            float4 v = ra[i];
            As[p][q * 8 + i * 4 + 0][row] = v.x;
            As[p][q * 8 + i * 4 + 1][row] = v.y;
            As[p][q * 8 + i * 4 + 2][row] = v.z;
            As[p][q * 8 + i * 4 + 3][row] = v.w;
        }
    };
    auto storeB = [&](int p) {
        int krow = tid >> 2, n0 = (tid & 3) * 16;
#pragma unroll
        for (int i = 0; i < 4; i++)
            *(float4*)&Bs[p][krow][n0 + i * 4] = rb[i];
    };

    float acc[4][4];
#pragma unroll
    for (int i = 0; i < 4; i++)
#pragma unroll
        for (int j = 0; j < 4; j++) acc[i][j] = 0.f;

    int nk = K / BK;
    loadA(0); loadB(0);
    storeA(0); storeB(0);
    __syncthreads();
    int p = 0;
    for (int it = 0; it < nk; it++) {
        if (it + 1 < nk) { loadA((it + 1) * BK); loadB((it + 1) * BK); }
#pragma unroll
        for (int k = 0; k < BK; k++) {
            float4 a4 = ld4(&As[p][k][trow * 4]);
            float4 b4 = ld4(&Bs[p][k][tcol * 4]);
            float a[4] = {a4.x, a4.y, a4.z, a4.w};
            float b[4] = {b4.x, b4.y, b4.z, b4.w};
#pragma unroll
            for (int i = 0; i < 4; i++)
#pragma unroll
                for (int j = 0; j < 4; j++) acc[i][j] += a[i] * b[j];
        }
        if (it + 1 < nk) { storeA(p ^ 1); storeB(p ^ 1); }
        __syncthreads();
        p ^= 1;
    }
#pragma unroll
    for (int i = 0; i < 4; i++) {
        int gm = bm + trow * 4 + i;
        if (gm >= M) continue;
#pragma unroll
        for (int j = 0; j < 4; j++) {
            int gn = bn + tcol * 4 + j;
            float v = acc[i][j];
            if (bias) v += bias[gn];
            if (ACT == 1) v = 0.5f * v * (1.f + erff(v * 0.70710678118654752f));
            size_t off = (size_t)gm * ldc + gn;
            if (ADDC) v += C[off];
            C[off] = v;
        }
    }
}

// ================= EdgeConv via per-point factorization =================
// y[edge r=(p,k)][o] = u[nbr][o] + v[p][o],  u = feat.w[:, :C], v = t2 - u
#define ECPT 8   // points per stats block
__global__ void ec_uv_stats(const float* __restrict__ u, const float* __restrict__ t2,
                            const int* __restrict__ knn, int O,
                            float* __restrict__ umax, float* __restrict__ umin,
                            float* __restrict__ psum, float* __restrict__ psq)
{
    __shared__ int sk[ECPT * KK];
    int blk = blockIdx.x;        // NPTS/ECPT blocks
    int o = threadIdx.x;         // O threads
    int base = blk * ECPT;
    for (int i = o; i < ECPT * KK; i += blockDim.x) {
        int p = base + i / KK;
        sk[i] = ((p >> 11) << 11) + knn[(size_t)base * KK + i];
    }
    __syncthreads();
    float S = 0.f, Q = 0.f;
    for (int pi = 0; pi < ECPT; pi++) {
        int p = base + pi;
        size_t po = (size_t)p * O + o;
        float up = u[po];
        float v = t2[po] - up;
        float mx = -FLT_MAX, mn = FLT_MAX;
#pragma unroll
        for (int k = 0; k < KK; k++) {
            float uu = u[(size_t)sk[pi * KK + k] * O + o];
            mx = fmaxf(mx, uu);
            mn = fminf(mn, uu);
            float y = uu + v;
            S += y;
            Q += y * y;
        }
        umax[po] = mx;
        umin[po] = mn;
    }
    psum[(size_t)blk * O + o] = S;
    psq[(size_t)blk * O + o] = Q;
}

// Dense apply: BN affine + lrelu of extremal u + v. No gather.
__global__ void ec_apply_uv(const float* __restrict__ u, const float* __restrict__ t2,
                            const float* __restrict__ umax, const float* __restrict__ umin,
                            const float* __restrict__ mean, const float* __restrict__ rstd,
                            const float* __restrict__ gam, const float* __restrict__ bet,
                            float* __restrict__ outH, int outOff, int O)
{
    int idx = blockIdx.x * blockDim.x + threadIdx.x;   // NPTS*O
    int p = idx / O, o = idx - p * O;
    float al = gam[o] * rstd[o];
    float be = bet[o] - mean[o] * al;
    float v = t2[idx] - u[idx];
    float m = (al >= 0.f) ? umax[idx] : umin[idx];
    float val = al * (m + v) + be;
    val = (val >= 0.f) ? val : 0.2f * val;
    outH[(size_t)p * 512 + outOff + o] = val;
}

// ---------------- deterministic BN finalize (strided partial layout) ----------------
__global__ void bn_reduce2(const float* __restrict__ psum, const float* __restrict__ psq,
                           int npart, int O, int bnsz, float cnt_inv,
                           float* __restrict__ mean, float* __restrict__ rstd)
{
    int o = blockIdx.x * blockDim.x + threadIdx.x;
    if (o >= O) return;
    int colblk = o / bnsz, c = o % bnsz;
    const float* ps = psum + (size_t)colblk * npart * bnsz + c;
    const float* pq = psq + (size_t)colblk * npart * bnsz + c;
    float s = 0.f, s2 = 0.f;
    for (int i = 0; i < npart; i++) {
        s  += ps[(size_t)i * bnsz];
        s2 += pq[(size_t)i * bnsz];
    }
    float mu = s * cnt_inv;
    float var = s2 * cnt_inv - mu * mu;
    mean[o] = mu;
    rstd[o] = rsqrtf(var + 1e-5f);
}

__global__ void diag_kernel(const float* __restrict__ G, float* __restrict__ sq)
{
    int bn = blockIdx.x * blockDim.x + threadIdx.x;
    if (bn < NPTS) {
        int b = bn >> 11, n = bn & 2047;
        sq[bn] = G[((size_t)b * NN + n) * NN + n];
    }
}

// ---------------- kNN select core (cached per-thread argmax) ----------------
#define KNN_SELECT_BODY(dist, out, bn)                                           \
    {                                                                            \
        float bv = -FLT_MAX; int bi = 0x7fffffff;                                \
        _Pragma("unroll")                                                        \
        for (int u2 = 0; u2 < NN / 256; u2++) {                                  \
            int j = u2 * 256 + tid;                                              \
            float v = dist[j];                                                   \
            if (v > bv) { bv = v; bi = j; }                                      \
        }                                                                        \
        for (int sel = 0; sel < KK; sel++) {                                     \
            float cv = bv; int ci = bi;                                          \
            _Pragma("unroll")                                                    \
            for (int off = 16; off > 0; off >>= 1) {                             \
                float ov = __shfl_down_sync(0xffffffffu, cv, off);               \
                int oi = __shfl_down_sync(0xffffffffu, ci, off);                 \
                if (ov > cv || (ov == cv && oi < ci)) { cv = ov; ci = oi; }      \
            }                                                                    \
            if (lane == 0) { wv[warp] = cv; wi[warp] = ci; }                     \
            __syncthreads();                                                     \
            if (tid == 0) {                                                      \
                float fv = wv[0]; int fi = wi[0];                                \
                _Pragma("unroll")                                                \
                for (int w = 1; w < 8; w++)                                      \
                    if (wv[w] > fv || (wv[w] == fv && wi[w] < fi)) {             \
                        fv = wv[w]; fi = wi[w];                                  \
                    }                                                            \
                out[(bn) * KK + sel] = fi;                                       \
                sfi = fi;                                                        \
            }                                                                    \
            __syncthreads();                                                     \
            int fi = sfi;                                                        \
            if ((fi & 255) == tid) {                                             \
                dist[fi] = -FLT_MAX;                                             \
                bv = -FLT_MAX; bi = 0x7fffffff;                                  \
                _Pragma("unroll")                                                \
                for (int u2 = 0; u2 < NN / 256; u2++) {                          \
                    int j = u2 * 256 + tid;                                      \
                    float v = dist[j];                                           \
                    if (v > bv) { bv = v; bi = j; }                              \
                }                                                                \
            }                                                                    \
        }                                                                        \
    }

__global__ void knn_select(const float* __restrict__ G, const float* __restrict__ sq,
                           int* __restrict__ out)
{
    int bn = blockIdx.x;
    int b = bn >> 11, n = bn & 2047;
    __shared__ float dist[NN];
    __shared__ float wv[8];
    __shared__ int wi[8];
    __shared__ int sfi;
    int tid = threadIdx.x;
    int lane = tid & 31, warp = tid >> 5;
    const float* row = G + ((size_t)b * NN + n) * NN;
    const float* sqb = sq + (b << 11);
    float sqn = sqb[n];
    for (int j = tid; j < NN; j += 256)
        dist[j] = 2.f * row[j] - sqn - sqb[j];
    __syncthreads();
    KNN_SELECT_BODY(dist, out, bn)
}

__global__ void knn_xyz(const float* __restrict__ x, int* __restrict__ out)
{
    int bn = blockIdx.x;
    int b = bn >> 11, n = bn & 2047;
    __shared__ float dist[NN];
    __shared__ float sx[NN], sy[NN], sz[NN], ssq[NN];
    __shared__ float wv[8];
    __shared__ int wi[8];
    __shared__ int sfi;
    int tid = threadIdx.x;
    int lane = tid & 31, warp = tid >> 5;
    const float* xb = x + (size_t)(b << 11) * 3;
    for (int j = tid; j < NN; j += 256) {
        float xv = xb[j * 3 + 0], yv = xb[j * 3 + 1], zv = xb[j * 3 + 2];
        sx[j] = xv; sy[j] = yv; sz[j] = zv;
        float s = 0.f;
        s = __fmaf_rn(xv, xv, s);
        s = __fmaf_rn(yv, yv, s);
        s = __fmaf_rn(zv, zv, s);
        ssq[j] = s;
    }
    __syncthreads();
    float xi = sx[n], yi = sy[n], zi = sz[n];
    float sqn = ssq[n];
    for (int j = tid; j < NN; j += 256) {
        float s = 0.f;
        s = __fmaf_rn(xi, sx[j], s);
        s = __fmaf_rn(yi, sy[j], s);
        s = __fmaf_rn(zi, sz[j], s);
        dist[j] = 2.f * s - sqn - ssq[j];
    }
    __syncthreads();
    KNN_SELECT_BODY(dist, out, bn)
}

// ---------------- conv5 BN partials ----------------
__global__ void bn5_partial(const float* __restrict__ y5, float* __restrict__ psum,
                            float* __restrict__ psq)
{
    int blk = blockIdx.x;
    int t0 = blk * 256;
    int tid = threadIdx.x;
    float s[4] = {0, 0, 0, 0}, s2[4] = {0, 0, 0, 0};
    for (int t = t0; t < t0 + 256; t++) {
        const float* row = y5 + (size_t)t * DD;
#pragma unroll
        for (int i = 0; i < 4; i++) {
            float v = row[tid + i * 256];
            s[i] += v; s2[i] += v * v;
        }
    }
#pragma unroll
    for (int i = 0; i < 4; i++) {
        psum[(size_t)blk * DD + tid + i * 256] = s[i];
        psq[(size_t)blk * DD + tid + i * 256] = s2[i];
    }
}

// ---------------- BN5 + leaky + patch max-pool + cls ----------------
__global__ void pool_kernel(const float* __restrict__ y5, const float* __restrict__ mean,
                            const float* __restrict__ rstd, const float* __restrict__ g5,
                            const float* __restrict__ b5, const float* __restrict__ cls,
                            float* __restrict__ t)
{
    int tok = blockIdx.x;
    int b = tok / 65, l = tok - b * 65;
    int tid = threadIdx.x;
    if (l == 0) {
        for (int d = tid; d < DD; d += 256) t[(size_t)tok * DD + d] = cls[d];
    } else {
        int p = l - 1;
        int base = b * NN + p * PS;
        for (int d = tid; d < DD; d += 256) {
            float mu = mean[d], rs = rstd[d], gg = g5[d], bb = b5[d];
            float m = -FLT_MAX;
            for (int s = 0; s < PS; s++) {
                float v = y5[(size_t)(base + s) * DD + d];
                v = (v - mu) * rs * gg + bb;
                v = (v >= 0.f) ? v : 0.2f * v;
                m = fmaxf(m, v);
            }
            t[(size_t)tok * DD + d] = m;
        }
    }
}

// ---------------- LayerNorm (optional fused pos-add) ----------------
__global__ void ln_kernel(float* __restrict__ t, const float* __restrict__ pos,
                          const float* __restrict__ g, const float* __restrict__ b,
                          float* __restrict__ out)
{
    int tok = blockIdx.x, tid = threadIdx.x;
    __shared__ float rs1[256], rs2[256];
    float* trow = t + (size_t)tok * DD;
    float loc[4];
    float s = 0.f, s2 = 0.f;
#pragma unroll
    for (int i = 0; i < 4; i++) {
        int d = tid + i * 256;
        float v = trow[d];
        if (pos) { v += pos[(size_t)tok * DD + d]; trow[d] = v; }
        loc[i] = v; s += v; s2 += v * v;
    }
    rs1[tid] = s; rs2[tid] = s2;
    __syncthreads();
    for (int st = 128; st > 0; st >>= 1) {
        if (tid < st) { rs1[tid] += rs1[tid + st]; rs2[tid] += rs2[tid + st]; }
        __syncthreads();
    }
    float mean = rs1[0] * (1.f / DD);
    float var = rs2[0] * (1.f / DD) - mean * mean;
    float rstd = rsqrtf(var + 1e-5f);
#pragma unroll
    for (int i = 0; i < 4; i++) {
        int d = tid + i * 256;
        out[(size_t)tok * DD + d] = (loc[i] - mean) * rstd * g[d] + b[d];
    }
}

// ---------------- attention ----------------
__global__ void attn_kernel(const float* __restrict__ qkv, float* __restrict__ z)
{
    int l = blockIdx.x, hh = blockIdx.y, b = blockIdx.z;
    int tid = threadIdx.x;   // 128
    __shared__ float sq_[64];
    __shared__ float sc[65];
    __shared__ float sinv;
    const float* qrow = qkv + (size_t)(b * 65 + l) * 1536 + hh * 64;
    if (tid < 64) sq_[tid] = qrow[tid];
    __syncthreads();
    if (tid < 65) {
        const float* krow = qkv + (size_t)(b * 65 + tid) * 1536 + 512 + hh * 64;
        float s = 0.f;
#pragma unroll 16
        for (int d = 0; d < 64; d++) s += sq_[d] * krow[d];
        sc[tid] = s * 0.125f;
    }
    __syncthreads();
    if (tid == 0) {
        float mx = -FLT_MAX;
        for (int m = 0; m < 65; m++) mx = fmaxf(mx, sc[m]);
        float sum = 0.f;
        for (int m = 0; m < 65; m++) { float e = expf(sc[m] - mx); sc[m] = e; sum += e; }
        sinv = 1.f / sum;
    }
    __syncthreads();
    if (tid < 64) {
        float inv = sinv;
        float acc = 0.f;
        for (int m = 0; m < 65; m++) {
            const float* vrow = qkv + (size_t)(b * 65 + m) * 1536 + 1024 + hh * 64;
            acc += sc[m] * vrow[tid];
        }
        z[(size_t)(b * 65 + l) * INNER + hh * 64 + tid] = acc * inv;
    }
}

__global__ void out_copy(const float* __restrict__ t, float* __restrict__ out)
{
    int i = blockIdx.x * blockDim.x + threadIdx.x;
    if (i < BB * PP * DD) {
        int d = i & (DD - 1);
        int bp = i >> 10;
        int b = bp >> 6, p = bp & 63;
        out[i] = t[((size_t)(b * 65 + 1 + p) << 10) + d];
    }
}

// ---------------- host driver ----------------
static void edge_layer(const float* featPtr, int lda, int C,
                       const float* w, const float* g, const float* b,
                       int O, int outOff, bool first, const float* xyz,
                       float* h, float* G, float* sq, int* knn,
                       float* u, float* t2, float* umax, float* umin,
                       float* psum, float* psq, float* mean, float* rstd)
{
    if (first) {
        knn_xyz<<<NPTS, 256>>>(xyz, knn);
    } else {
        dim3 gg(NN / 128, NN / 128, BB);
        gemm128<true, 0, false><<<gg, 256>>>(
            featPtr, lda, (size_t)NN * lda, featPtr, lda, (size_t)NN * lda,
            nullptr, G, NN, (size_t)NN * NN, NN, NN, C);
        diag_kernel<<<(NPTS + 255) / 256, 256>>>(G, sq);
        knn_select<<<NPTS, 256>>>(G, sq, knn);
    }
    int C2 = 2 * C;
    dim3 gu((O + 127) / 128, NPTS / 128);
    gemm128<true, 0, false><<<gu, 256>>>(featPtr, lda, 0, w, C2, 0, nullptr,
                                         u, O, 0, NPTS, O, C);
    gemm128<true, 0, false><<<gu, 256>>>(featPtr, lda, 0, w + C, C2, 0, nullptr,
                                         t2, O, 0, NPTS, O, C);
    ec_uv_stats<<<NPTS / ECPT, O>>>(u, t2, knn, O, umax, umin, psum, psq);
    bn_reduce2<<<(O + 255) / 256, 256>>>(psum, psq, NPTS / ECPT, O, O,
                                         1.f / (float)EROWS, mean, rstd);
    ec_apply_uv<<<NPTS * O / 256, 256>>>(u, t2, umax, umin, mean, rstd, g, b,
                                         h, outOff, O);
}

extern "C" void kernel_launch(void* const* d_in, const int* in_sizes, int n_in,
                              void* d_out, int out_size)
{
    const float* x      = (const float*)d_in[0];
    const float* pos    = (const float*)d_in[1];
    const float* w1 = (const float*)d_in[2];  const float* g1 = (const float*)d_in[3];  const float* b1 = (const float*)d_in[4];
    const float* w2 = (const float*)d_in[5];  const float* g2 = (const float*)d_in[6];  const float* b2 = (const float*)d_in[7];
    const float* w3 = (const float*)d_in[8];  const float* g3 = (const float*)d_in[9];  const float* b3 = (const float*)d_in[10];
    const float* w4 = (const float*)d_in[11]; const float* g4 = (const float*)d_in[12]; const float* b4 = (const float*)d_in[13];
    const float* w5 = (const float*)d_in[14]; const float* g5 = (const float*)d_in[15]; const float* b5 = (const float*)d_in[16];
    const float* cls    = (const float*)d_in[17];
    const float* ln1g   = (const float*)d_in[18];
    const float* ln1b   = (const float*)d_in[19];
    const float* wqkv   = (const float*)d_in[20];
    const float* wout   = (const float*)d_in[21];
    const float* bout   = (const float*)d_in[22];
    const float* ln2g   = (const float*)d_in[23];
    const float* ln2b   = (const float*)d_in[24];
    const float* wff1   = (const float*)d_in[25];
    const float* bff1   = (const float*)d_in[26];
    const float* wff2   = (const float*)d_in[27];
    const float* bff2   = (const float*)d_in[28];
    float* out = (float*)d_out;

    float *h, *G, *sq, *u, *t2, *umax, *umin, *psum, *psq, *mean, *rstd;
    float *y5, *t, *ln, *qkv, *z, *ff;
    int* knn;
    cudaGetSymbolAddress((void**)&h, g_h);
    cudaGetSymbolAddress((void**)&G, g_G);
    cudaGetSymbolAddress((void**)&sq, g_sq);
    cudaGetSymbolAddress((void**)&knn, g_knn);
    cudaGetSymbolAddress((void**)&u, g_u);
    cudaGetSymbolAddress((void**)&t2, g_t2);
    cudaGetSymbolAddress((void**)&umax, g_umax);
    cudaGetSymbolAddress((void**)&umin, g_umin);
    cudaGetSymbolAddress((void**)&psum, g_psum);
    cudaGetSymbolAddress((void**)&psq, g_psq);
    cudaGetSymbolAddress((void**)&mean, g_mean);
    cudaGetSymbolAddress((void**)&rstd, g_rstd);
    cudaGetSymbolAddress((void**)&y5, g_y5);
    cudaGetSymbolAddress((void**)&t, g_t);
    cudaGetSymbolAddress((void**)&ln, g_ln);
    cudaGetSymbolAddress((void**)&qkv, g_qkv);
    cudaGetSymbolAddress((void**)&z, g_z);
    cudaGetSymbolAddress((void**)&ff, g_ff);

    // ---- DGCNN backbone (factorized EdgeConv) ----
    edge_layer(x,       3,   3,   w1, g1, b1, 64,  0,   true,  x,
               h, G, sq, knn, u, t2, umax, umin, psum, psq, mean, rstd);
    edge_layer(h + 0,   512, 64,  w2, g2, b2, 64,  64,  false, nullptr,
               h, G, sq, knn, u, t2, umax, umin, psum, psq, mean, rstd);
    edge_layer(h + 64,  512, 64,  w3, g3, b3, 128, 128, false, nullptr,
               h, G, sq, knn, u, t2, umax, umin, psum, psq, mean, rstd);
    edge_layer(h + 128, 512, 128, w4, g4, b4, 256, 256, false, nullptr,
               h, G, sq, knn, u, t2, umax, umin, psum, psq, mean, rstd);

    // ---- conv5 ----
    {
        dim3 gg(DD / 128, NPTS / 128);
        gemm128<true, 0, false><<<gg, 256>>>(
            h, 512, 0, w5, 512, 0, nullptr, y5, DD, 0, NPTS, DD, 512);
        bn5_partial<<<NPTS / 256, 256>>>(y5, psum, psq);
        bn_reduce2<<<(DD + 255) / 256, 256>>>(psum, psq, NPTS / 256, DD, DD,
                                              1.f / (8.f * 2048.f), mean, rstd);
        pool_kernel<<<TOK, 256>>>(y5, mean, rstd, g5, b5, cls, t);
    }

    // ---- transformer ----
    for (int i = 0; i < 6; i++) {
        const float* wqkv_i = wqkv + (size_t)i * DD * 3 * INNER;
        const float* wout_i = wout + (size_t)i * INNER * DD;
        const float* bout_i = bout + (size_t)i * DD;
        const float* wff1_i = wff1 + (size_t)i * DD * MLPD;
        const float* bff1_i = bff1 + (size_t)i * MLPD;
        const float* wff2_i = wff2 + (size_t)i * MLPD * DD;
        const float* bff2_i = bff2 + (size_t)i * DD;

        ln_kernel<<<TOK, 256>>>(t, pos, ln1g + i * DD, ln1b + i * DD, ln);

        dim3 gq(3 * INNER / 64, (TOK + 31) / 32);
        gemm32<0, false><<<gq, 128>>>(ln, DD, wqkv_i, 3 * INNER, nullptr,
                                      qkv, 3 * INNER, TOK, 3 * INNER, DD);

        attn_kernel<<<dim3(65, 8, BB), 128>>>(qkv, z);

        dim3 gp(DD / 64, (TOK + 31) / 32);
        gemm32<0, true><<<gp, 128>>>(z, INNER, wout_i, DD, bout_i,
                                     t, DD, TOK, DD, INNER);

        ln_kernel<<<TOK, 256>>>(t, nullptr, ln2g + i * DD, ln2b + i * DD, ln);

        dim3 gf1(MLPD / 64, (TOK + 31) / 32);
        gemm32<1, false><<<gf1, 128>>>(ln, DD, wff1_i, MLPD, bff1_i,
                                       ff, MLPD, TOK, MLPD, DD);

        dim3 gf2(DD / 64, (TOK + 31) / 32);
        gemm32<0, true><<<gf2, 128>>>(ff, MLPD, wff2_i, DD, bff2_i,
                                      t, DD, TOK, DD, MLPD);
    }

    out_copy<<<(BB * PP * DD + 255) / 256, 256>>>(t, out);
}

// round 14
// speedup vs baseline: 1.0649x; 1.0649x over previous
#include <cuda_runtime.h>
#include <cuda_bf16.h>
#include <cfloat>
#include <math.h>

// ---------------- problem constants ----------------
#define BB 8
#define NN 2048
#define KK 20
#define PP 64
#define PS 32
#define DD 1024
#define TOK (BB * (PP + 1))   // 520
#define INNER 512
#define MLPD 2048
#define EROWS (BB * NN * KK)  // 327680
#define NPTS (BB * NN)        // 16384
#define ECPT 8                // points per stats block

// ---------------- scratch ----------------
__device__ float g_h[NPTS * 512];
__device__ float g_G[BB * NN * NN];
__device__ float g_sq[NPTS];
__device__ int   g_knn[EROWS];
__device__ float g_ut[NPTS * 512];      // interleaved u/t2: [p][2o]=u, [p][2o+1]=t2
__device__ float g_umax[NPTS * 256];
__device__ float g_umin[NPTS * 256];
__device__ float g_psum[2048 * 256];
__device__ float g_psq[2048 * 256];
__device__ float g_mean[1024];
__device__ float g_rstd[1024];
__device__ float g_y5[NPTS * DD];
__device__ float g_t[TOK * DD];
__device__ float g_ln[TOK * DD];
__device__ float g_qkv[TOK * 3 * INNER];
__device__ float g_z[TOK * INNER];
__device__ float g_ff[TOK * MLPD];

__device__ __forceinline__ float4 ld4(const float* p) { return *(const float4*)p; }

// ================= double-buffered 128x128x16 SGEMM (gram / conv5 / uv) =================
template <bool TRANSB, int ACT, bool ADDC>
__global__ __launch_bounds__(256, 2)
void gemm128(const float* __restrict__ A, int lda, size_t strideA,
             const float* __restrict__ Bm, int ldb, size_t strideB,
             const float* __restrict__ bias,
             float* __restrict__ C, int ldc, size_t strideC,
             int M, int N, int K)
{
    const int BK = 16;
    __shared__ float As[2][BK][128];
    __shared__ float Bs[2][BK][128];
    A  += (size_t)blockIdx.z * strideA;
    Bm += (size_t)blockIdx.z * strideB;
    C  += (size_t)blockIdx.z * strideC;
    int bm = blockIdx.y * 128, bn = blockIdx.x * 128;
    int tid = threadIdx.x;
    int trow = tid >> 4, tcol = tid & 15;

    float4 ra[2], rb[2];

    auto loadA = [&](int k0) {
#pragma unroll
        for (int i = 0; i < 2; i++) {
            int row = i * 64 + (tid >> 2), q = tid & 3;
            int gm = bm + row, gk = k0 + q * 4;
            if (k0 + BK <= K) {
                ra[i] = (gm < M) ? ld4(&A[(size_t)gm * lda + gk]) : make_float4(0, 0, 0, 0);
            } else {
                float v[4];
#pragma unroll
                for (int j = 0; j < 4; j++)
                    v[j] = (gm < M && gk + j < K) ? A[(size_t)gm * lda + gk + j] : 0.f;
                ra[i] = make_float4(v[0], v[1], v[2], v[3]);
            }
        }
    };
    auto loadB = [&](int k0) {
#pragma unroll
        for (int i = 0; i < 2; i++) {
            if (TRANSB) {
                int row = i * 64 + (tid >> 2), q = tid & 3;
                int gn = bn + row, gk = k0 + q * 4;
                if (k0 + BK <= K) {
                    rb[i] = (gn < N) ? ld4(&Bm[(size_t)gn * ldb + gk]) : make_float4(0, 0, 0, 0);
                } else {
                    float v[4];
#pragma unroll
                    for (int j = 0; j < 4; j++)
                        v[j] = (gn < N && gk + j < K) ? Bm[(size_t)gn * ldb + gk + j] : 0.f;
                    rb[i] = make_float4(v[0], v[1], v[2], v[3]);
                }
            } else {
                int krow = i * 8 + (tid >> 5), nq = tid & 31;
                int gk = k0 + krow, gn = bn + nq * 4;
                if (gk < K && gn < N) rb[i] = ld4(&Bm[(size_t)gk * ldb + gn]);
                else rb[i] = make_float4(0, 0, 0, 0);
            }
        }
    };
    auto storeA = [&](int p) {
#pragma unroll
        for (int i = 0; i < 2; i++) {
            int row = i * 64 + (tid >> 2), q = tid & 3;
            As[p][q * 4 + 0][row] = ra[i].x;
            As[p][q * 4 + 1][row] = ra[i].y;
            As[p][q * 4 + 2][row] = ra[i].z;
            As[p][q * 4 + 3][row] = ra[i].w;
        }
    };
    auto storeB = [&](int p) {
#pragma unroll
        for (int i = 0; i < 2; i++) {
            if (TRANSB) {
                int row = i * 64 + (tid >> 2), q = tid & 3;
                Bs[p][q * 4 + 0][row] = rb[i].x;
                Bs[p][q * 4 + 1][row] = rb[i].y;
                Bs[p][q * 4 + 2][row] = rb[i].z;
                Bs[p][q * 4 + 3][row] = rb[i].w;
            } else {
                int krow = i * 8 + (tid >> 5), nq = tid & 31;
                *(float4*)&Bs[p][krow][nq * 4] = rb[i];
            }
        }
    };

    float acc[8][8];
#pragma unroll
    for (int i = 0; i < 8; i++)
#pragma unroll
        for (int j = 0; j < 8; j++) acc[i][j] = 0.f;

    int nk = (K + BK - 1) / BK;
    loadA(0); loadB(0);
    storeA(0); storeB(0);
    __syncthreads();
    int p = 0;
    for (int it = 0; it < nk; it++) {
        if (it + 1 < nk) { loadA((it + 1) * BK); loadB((it + 1) * BK); }
#pragma unroll
        for (int k = 0; k < BK; k++) {
            float4 a0 = ld4(&As[p][k][trow * 8]);
            float4 a1 = ld4(&As[p][k][trow * 8 + 4]);
            float4 b0 = ld4(&Bs[p][k][tcol * 8]);
            float4 b1 = ld4(&Bs[p][k][tcol * 8 + 4]);
            float a[8] = {a0.x, a0.y, a0.z, a0.w, a1.x, a1.y, a1.z, a1.w};
            float b[8] = {b0.x, b0.y, b0.z, b0.w, b1.x, b1.y, b1.z, b1.w};
#pragma unroll
            for (int i = 0; i < 8; i++)
#pragma unroll
                for (int j = 0; j < 8; j++) acc[i][j] += a[i] * b[j];
        }
        if (it + 1 < nk) { storeA(p ^ 1); storeB(p ^ 1); }
        __syncthreads();
        p ^= 1;
    }
#pragma unroll
    for (int i = 0; i < 8; i++) {
        int gm = bm + trow * 8 + i;
        if (gm >= M) continue;
#pragma unroll
        for (int j = 0; j < 8; j++) {
            int gn = bn + tcol * 8 + j;
            if (gn >= N) continue;
            float v = acc[i][j];
            if (bias) v += bias[gn];
            if (ACT == 1) v = 0.5f * v * (1.f + erff(v * 0.70710678118654752f));
            size_t off = (size_t)gm * ldc + gn;
            if (ADDC) v += C[off];
            C[off] = v;
        }
    }
}

// ================= double-buffered 64x64x32 SGEMM (transformer, B=[K,N]) =================
template <int ACT, bool ADDC>
__global__ __launch_bounds__(256)
void gemm64(const float* __restrict__ A, int lda,
            const float* __restrict__ Bm, int ldb,
            const float* __restrict__ bias,
            float* __restrict__ C, int ldc,
            int M, int N, int K)
{
    const int BK = 32;
    __shared__ float As[2][BK][64];
    __shared__ float Bs[2][BK][64];
    int bm = blockIdx.y * 64, bn = blockIdx.x * 64;
    int tid = threadIdx.x;
    int trow = tid >> 4, tcol = tid & 15;
    float4 ra[2], rb[2];

    auto loadA = [&](int k0) {
        int row = tid >> 2, q = tid & 3;
        int gm = bm + row, gk = k0 + q * 8;
        if (gm < M) {
            ra[0] = ld4(&A[(size_t)gm * lda + gk]);
            ra[1] = ld4(&A[(size_t)gm * lda + gk + 4]);
        } else {
            ra[0] = make_float4(0, 0, 0, 0);
            ra[1] = make_float4(0, 0, 0, 0);
        }
    };
    auto loadB = [&](int k0) {
        int krow = tid >> 3, gn = bn + (tid & 7) * 8;
        int gk = k0 + krow;
        rb[0] = ld4(&Bm[(size_t)gk * ldb + gn]);
        rb[1] = ld4(&Bm[(size_t)gk * ldb + gn + 4]);
    };
    auto storeA = [&](int p) {
        int row = tid >> 2, q = tid & 3;
#pragma unroll
        for (int i = 0; i < 2; i++) {
            As[p][q * 8 + i * 4 + 0][row] = (i ? ra[1].x : ra[0].x);
            As[p][q * 8 + i * 4 + 1][row] = (i ? ra[1].y : ra[0].y);
            As[p][q * 8 + i * 4 + 2][row] = (i ? ra[1].z : ra[0].z);
            As[p][q * 8 + i * 4 + 3][row] = (i ? ra[1].w : ra[0].w);
        }
    };
    auto storeB = [&](int p) {
        int krow = tid >> 3, nq = (tid & 7) * 8;
        *(float4*)&Bs[p][krow][nq] = rb[0];
        *(float4*)&Bs[p][krow][nq + 4] = rb[1];
    };

    float acc[4][4];
#pragma unroll
    for (int i = 0; i < 4; i++)
#pragma unroll
        for (int j = 0; j < 4; j++) acc[i][j] = 0.f;

    int nk = K / BK;
    loadA(0); loadB(0);
    storeA(0); storeB(0);
    __syncthreads();
    int p = 0;
    for (int it = 0; it < nk; it++) {
        if (it + 1 < nk) { loadA((it + 1) * BK); loadB((it + 1) * BK); }
#pragma unroll
        for (int k = 0; k < BK; k++) {
            float4 a4 = ld4(&As[p][k][trow * 4]);
            float4 b4 = ld4(&Bs[p][k][tcol * 4]);
            float a[4] = {a4.x, a4.y, a4.z, a4.w};
            float b[4] = {b4.x, b4.y, b4.z, b4.w};
#pragma unroll
            for (int i = 0; i < 4; i++)
#pragma unroll
                for (int j = 0; j < 4; j++) acc[i][j] += a[i] * b[j];
        }
        if (it + 1 < nk) { storeA(p ^ 1); storeB(p ^ 1); }
        __syncthreads();
        p ^= 1;
    }
#pragma unroll
    for (int i = 0; i < 4; i++) {
        int gm = bm + trow * 4 + i;
        if (gm >= M) continue;
#pragma unroll
        for (int j = 0; j < 4; j++) {
            int gn = bn + tcol * 4 + j;
            float v = acc[i][j];
            if (bias) v += bias[gn];
            if (ACT == 1) v = 0.5f * v * (1.f + erff(v * 0.70710678118654752f));
            size_t off = (size_t)gm * ldc + gn;
            if (ADDC) v += C[off];
            C[off] = v;
        }
    }
}

// ================= EdgeConv via per-point factorization (interleaved ut) =================
// ut[p][2o] = u = feat.w[o,:C]; ut[p][2o+1] = t2 = feat.w[o,C:]
// y[edge (p,k)][o] = u[nbr] + (t2[p]-u[p])
__global__ void ec_uv_stats(const float* __restrict__ ut,
                            const int* __restrict__ knn, int O,
                            float* __restrict__ umax, float* __restrict__ umin,
                            float* __restrict__ psum, float* __restrict__ psq)
{
    __shared__ int sk[ECPT * KK];
    int blk = blockIdx.x;
    int o = threadIdx.x;         // O threads
    int base = blk * ECPT;
    int O2 = 2 * O;
    for (int i = o; i < ECPT * KK; i += blockDim.x) {
        int p = base + i / KK;
        sk[i] = ((p >> 11) << 11) + knn[(size_t)base * KK + i];
    }
    __syncthreads();
    float S = 0.f, Q = 0.f;
    for (int pi = 0; pi < ECPT; pi++) {
        int p = base + pi;
        float2 uv = *(const float2*)&ut[(size_t)p * O2 + 2 * o];
        float v = uv.y - uv.x;
        float mx = -FLT_MAX, mn = FLT_MAX;
#pragma unroll
        for (int k = 0; k < KK; k++) {
            float uu = ut[(size_t)sk[pi * KK + k] * O2 + 2 * o];
            mx = fmaxf(mx, uu);
            mn = fminf(mn, uu);
            float y = uu + v;
            S += y;
            Q += y * y;
        }
        umax[(size_t)p * O + o] = mx;
        umin[(size_t)p * O + o] = mn;
    }
    psum[(size_t)blk * O + o] = S;
    psq[(size_t)blk * O + o] = Q;
}

// Dense apply: BN affine + lrelu of extremal u + v. No gather.
__global__ void ec_apply_uv(const float* __restrict__ ut,
                            const float* __restrict__ umax, const float* __restrict__ umin,
                            const float* __restrict__ mean, const float* __restrict__ rstd,
                            const float* __restrict__ gam, const float* __restrict__ bet,
                            float* __restrict__ outH, int outOff, int O)
{
    int idx = blockIdx.x * blockDim.x + threadIdx.x;   // NPTS*O
    int p = idx / O, o = idx - p * O;
    float al = gam[o] * rstd[o];
    float be = bet[o] - mean[o] * al;
    float2 uv = *(const float2*)&ut[(size_t)p * 2 * O + 2 * o];
    float v = uv.y - uv.x;
    float m = (al >= 0.f) ? umax[idx] : umin[idx];
    float val = al * (m + v) + be;
    val = (val >= 0.f) ? val : 0.2f * val;
    outH[(size_t)p * 512 + outOff + o] = val;
}

// ---------------- deterministic BN finalize (strided partial layout) ----------------
__global__ void bn_reduce2(const float* __restrict__ psum, const float* __restrict__ psq,
                           int npart, int O, int bnsz, float cnt_inv,
                           float* __restrict__ mean, float* __restrict__ rstd)
{
    int o = blockIdx.x * blockDim.x + threadIdx.x;
    if (o >= O) return;
    int colblk = o / bnsz, c = o % bnsz;
    const float* ps = psum + (size_t)colblk * npart * bnsz + c;
    const float* pq = psq + (size_t)colblk * npart * bnsz + c;
    float s = 0.f, s2 = 0.f;
    for (int i = 0; i < npart; i++) {
        s  += ps[(size_t)i * bnsz];
        s2 += pq[(size_t)i * bnsz];
    }
    float mu = s * cnt_inv;
    float var = s2 * cnt_inv - mu * mu;
    mean[o] = mu;
    rstd[o] = rsqrtf(var + 1e-5f);
}

__global__ void diag_kernel(const float* __restrict__ G, float* __restrict__ sq)
{
    int bn = blockIdx.x * blockDim.x + threadIdx.x;
    if (bn < NPTS) {
        int b = bn >> 11, n = bn & 2047;
        sq[bn] = G[((size_t)b * NN + n) * NN + n];
    }
}

// ---------------- kNN select core (cached per-thread argmax) ----------------
#define KNN_SELECT_BODY(dist, out, bn)                                           \
    {                                                                            \
        float bv = -FLT_MAX; int bi = 0x7fffffff;                                \
        _Pragma("unroll")                                                        \
        for (int u2 = 0; u2 < NN / 256; u2++) {                                  \
            int j = u2 * 256 + tid;                                              \
            float v = dist[j];                                                   \
            if (v > bv) { bv = v; bi = j; }                                      \
        }                                                                        \
        for (int sel = 0; sel < KK; sel++) {                                     \
            float cv = bv; int ci = bi;                                          \
            _Pragma("unroll")                                                    \
            for (int off = 16; off > 0; off >>= 1) {                             \
                float ov = __shfl_down_sync(0xffffffffu, cv, off);               \
                int oi = __shfl_down_sync(0xffffffffu, ci, off);                 \
                if (ov > cv || (ov == cv && oi < ci)) { cv = ov; ci = oi; }      \
            }                                                                    \
            if (lane == 0) { wv[warp] = cv; wi[warp] = ci; }                     \
            __syncthreads();                                                     \
            if (tid == 0) {                                                      \
                float fv = wv[0]; int fi = wi[0];                                \
                _Pragma("unroll")                                                \
                for (int w = 1; w < 8; w++)                                      \
                    if (wv[w] > fv || (wv[w] == fv && wi[w] < fi)) {             \
                        fv = wv[w]; fi = wi[w];                                  \
                    }                                                            \
                out[(bn) * KK + sel] = fi;                                       \
                sfi = fi;                                                        \
            }                                                                    \
            __syncthreads();                                                     \
            int fi = sfi;                                                        \
            if ((fi & 255) == tid) {                                             \
                dist[fi] = -FLT_MAX;                                             \
                bv = -FLT_MAX; bi = 0x7fffffff;                                  \
                _Pragma("unroll")                                                \
                for (int u2 = 0; u2 < NN / 256; u2++) {                          \
                    int j = u2 * 256 + tid;                                      \
                    float v = dist[j];                                           \
                    if (v > bv) { bv = v; bi = j; }                              \
                }                                                                \
            }                                                                    \
        }                                                                        \
    }

__global__ void knn_select(const float* __restrict__ G, const float* __restrict__ sq,
                           int* __restrict__ out)
{
    int bn = blockIdx.x;
    int b = bn >> 11, n = bn & 2047;
    __shared__ float dist[NN];
    __shared__ float wv[8];
    __shared__ int wi[8];
    __shared__ int sfi;
    int tid = threadIdx.x;
    int lane = tid & 31, warp = tid >> 5;
    const float* row = G + ((size_t)b * NN + n) * NN;
    const float* sqb = sq + (b << 11);
    float sqn = sqb[n];
    for (int j = tid; j < NN; j += 256)
        dist[j] = 2.f * row[j] - sqn - sqb[j];
    __syncthreads();
    KNN_SELECT_BODY(dist, out, bn)
}

__global__ void knn_xyz(const float* __restrict__ x, int* __restrict__ out)
{
    int bn = blockIdx.x;
    int b = bn >> 11, n = bn & 2047;
    __shared__ float dist[NN];
    __shared__ float sx[NN], sy[NN], sz[NN], ssq[NN];
    __shared__ float wv[8];
    __shared__ int wi[8];
    __shared__ int sfi;
    int tid = threadIdx.x;
    int lane = tid & 31, warp = tid >> 5;
    const float* xb = x + (size_t)(b << 11) * 3;
    for (int j = tid; j < NN; j += 256) {
        float xv = xb[j * 3 + 0], yv = xb[j * 3 + 1], zv = xb[j * 3 + 2];
        sx[j] = xv; sy[j] = yv; sz[j] = zv;
        float s = 0.f;
        s = __fmaf_rn(xv, xv, s);
        s = __fmaf_rn(yv, yv, s);
        s = __fmaf_rn(zv, zv, s);
        ssq[j] = s;
    }
    __syncthreads();
    float xi = sx[n], yi = sy[n], zi = sz[n];
    float sqn = ssq[n];
    for (int j = tid; j < NN; j += 256) {
        float s = 0.f;
        s = __fmaf_rn(xi, sx[j], s);
        s = __fmaf_rn(yi, sy[j], s);
        s = __fmaf_rn(zi, sz[j], s);
        dist[j] = 2.f * s - sqn - ssq[j];
    }
    __syncthreads();
    KNN_SELECT_BODY(dist, out, bn)
}

// ---------------- conv5 BN partials ----------------
__global__ void bn5_partial(const float* __restrict__ y5, float* __restrict__ psum,
                            float* __restrict__ psq)
{
    int blk = blockIdx.x;
    int t0 = blk * 256;
    int tid = threadIdx.x;
    float s[4] = {0, 0, 0, 0}, s2[4] = {0, 0, 0, 0};
    for (int t = t0; t < t0 + 256; t++) {
        const float* row = y5 + (size_t)t * DD;
#pragma unroll
        for (int i = 0; i < 4; i++) {
            float v = row[tid + i * 256];
            s[i] += v; s2[i] += v * v;
        }
    }
#pragma unroll
    for (int i = 0; i < 4; i++) {
        psum[(size_t)blk * DD + tid + i * 256] = s[i];
        psq[(size_t)blk * DD + tid + i * 256] = s2[i];
    }
}

// ---------------- BN5 + leaky + patch max-pool + cls ----------------
__global__ void pool_kernel(const float* __restrict__ y5, const float* __restrict__ mean,
                            const float* __restrict__ rstd, const float* __restrict__ g5,
                            const float* __restrict__ b5, const float* __restrict__ cls,
                            float* __restrict__ t)
{
    int tok = blockIdx.x;
    int b = tok / 65, l = tok - b * 65;
    int tid = threadIdx.x;
    if (l == 0) {
        for (int d = tid; d < DD; d += 256) t[(size_t)tok * DD + d] = cls[d];
    } else {
        int p = l - 1;
        int base = b * NN + p * PS;
        for (int d = tid; d < DD; d += 256) {
            float mu = mean[d], rs = rstd[d], gg = g5[d], bb = b5[d];
            float m = -FLT_MAX;
            for (int s = 0; s < PS; s++) {
                float v = y5[(size_t)(base + s) * DD + d];
                v = (v - mu) * rs * gg + bb;
                v = (v >= 0.f) ? v : 0.2f * v;
                m = fmaxf(m, v);
            }
            t[(size_t)tok * DD + d] = m;
        }
    }
}

// ---------------- LayerNorm (optional fused pos-add) ----------------
__global__ void ln_kernel(float* __restrict__ t, const float* __restrict__ pos,
                          const float* __restrict__ g, const float* __restrict__ b,
                          float* __restrict__ out)
{
    int tok = blockIdx.x, tid = threadIdx.x;
    __shared__ float rs1[256], rs2[256];
    float* trow = t + (size_t)tok * DD;
    float loc[4];
    float s = 0.f, s2 = 0.f;
#pragma unroll
    for (int i = 0; i < 4; i++) {
        int d = tid + i * 256;
        float v = trow[d];
        if (pos) { v += pos[(size_t)tok * DD + d]; trow[d] = v; }
        loc[i] = v; s += v; s2 += v * v;
    }
    rs1[tid] = s; rs2[tid] = s2;
    __syncthreads();
    for (int st = 128; st > 0; st >>= 1) {
        if (tid < st) { rs1[tid] += rs1[tid + st]; rs2[tid] += rs2[tid + st]; }
        __syncthreads();
    }
    float mean = rs1[0] * (1.f / DD);
    float var = rs2[0] * (1.f / DD) - mean * mean;
    float rstd = rsqrtf(var + 1e-5f);
#pragma unroll
    for (int i = 0; i < 4; i++) {
        int d = tid + i * 256;
        out[(size_t)tok * DD + d] = (loc[i] - mean) * rstd * g[d] + b[d];
    }
}

// ---------------- attention ----------------
__global__ void attn_kernel(const float* __restrict__ qkv, float* __restrict__ z)
{
    int l = blockIdx.x, hh = blockIdx.y, b = blockIdx.z;
    int tid = threadIdx.x;   // 128
    __shared__ float sq_[64];
    __shared__ float sc[65];
    __shared__ float sinv;
    const float* qrow = qkv + (size_t)(b * 65 + l) * 1536 + hh * 64;
    if (tid < 64) sq_[tid] = qrow[tid];
    __syncthreads();
    if (tid < 65) {
        const float* krow = qkv + (size_t)(b * 65 + tid) * 1536 + 512 + hh * 64;
        float s = 0.f;
#pragma unroll 16
        for (int d = 0; d < 64; d++) s += sq_[d] * krow[d];
        sc[tid] = s * 0.125f;
    }
    __syncthreads();
    if (tid == 0) {
        float mx = -FLT_MAX;
        for (int m = 0; m < 65; m++) mx = fmaxf(mx, sc[m]);
        float sum = 0.f;
        for (int m = 0; m < 65; m++) { float e = expf(sc[m] - mx); sc[m] = e; sum += e; }
        sinv = 1.f / sum;
    }
    __syncthreads();
    if (tid < 64) {
        float inv = sinv;
        float acc = 0.f;
        for (int m = 0; m < 65; m++) {
            const float* vrow = qkv + (size_t)(b * 65 + m) * 1536 + 1024 + hh * 64;
            acc += sc[m] * vrow[tid];
        }
        z[(size_t)(b * 65 + l) * INNER + hh * 64 + tid] = acc * inv;
    }
}

__global__ void out_copy(const float* __restrict__ t, float* __restrict__ out)
{
    int i = blockIdx.x * blockDim.x + threadIdx.x;
    if (i < BB * PP * DD) {
        int d = i & (DD - 1);
        int bp = i >> 10;
        int b = bp >> 6, p = bp & 63;
        out[i] = t[((size_t)(b * 65 + 1 + p) << 10) + d];
    }
}

// ---------------- host driver ----------------
static void edge_layer(const float* featPtr, int lda, int C,
                       const float* w, const float* g, const float* b,
                       int O, int outOff, bool first, const float* xyz,
                       float* h, float* G, float* sq, int* knn,
                       float* ut, float* umax, float* umin,
                       float* psum, float* psq, float* mean, float* rstd)
{
    if (first) {
        knn_xyz<<<NPTS, 256>>>(xyz, knn);
    } else {
        dim3 gg(NN / 128, NN / 128, BB);
        gemm128<true, 0, false><<<gg, 256>>>(
            featPtr, lda, (size_t)NN * lda, featPtr, lda, (size_t)NN * lda,
            nullptr, G, NN, (size_t)NN * NN, NN, NN, C);
        diag_kernel<<<(NPTS + 255) / 256, 256>>>(G, sq);
        knn_select<<<NPTS, 256>>>(G, sq, knn);
    }
    // Fused u/t2 GEMM: view w[O,2C] as [2O, C] row-major (ldb = C):
    //   row 2o   = w[o, :C]   -> ut[p][2o]   = u
    //   row 2o+1 = w[o, C:2C] -> ut[p][2o+1] = t2
    int O2 = 2 * O;
    dim3 gu((O2 + 127) / 128, NPTS / 128);
    gemm128<true, 0, false><<<gu, 256>>>(featPtr, lda, 0, w, C, 0, nullptr,
                                         ut, O2, 0, NPTS, O2, C);
    ec_uv_stats<<<NPTS / ECPT, O>>>(ut, knn, O, umax, umin, psum, psq);
    bn_reduce2<<<(O + 255) / 256, 256>>>(psum, psq, NPTS / ECPT, O, O,
                                         1.f / (float)EROWS, mean, rstd);
    ec_apply_uv<<<NPTS * O / 256, 256>>>(ut, umax, umin, mean, rstd, g, b,
                                         h, outOff, O);
}

extern "C" void kernel_launch(void* const* d_in, const int* in_sizes, int n_in,
                              void* d_out, int out_size)
{
    const float* x      = (const float*)d_in[0];
    const float* pos    = (const float*)d_in[1];
    const float* w1 = (const float*)d_in[2];  const float* g1 = (const float*)d_in[3];  const float* b1 = (const float*)d_in[4];
    const float* w2 = (const float*)d_in[5];  const float* g2 = (const float*)d_in[6];  const float* b2 = (const float*)d_in[7];
    const float* w3 = (const float*)d_in[8];  const float* g3 = (const float*)d_in[9];  const float* b3 = (const float*)d_in[10];
    const float* w4 = (const float*)d_in[11]; const float* g4 = (const float*)d_in[12]; const float* b4 = (const float*)d_in[13];
    const float* w5 = (const float*)d_in[14]; const float* g5 = (const float*)d_in[15]; const float* b5 = (const float*)d_in[16];
    const float* cls    = (const float*)d_in[17];
    const float* ln1g   = (const float*)d_in[18];
    const float* ln1b   = (const float*)d_in[19];
    const float* wqkv   = (const float*)d_in[20];
    const float* wout   = (const float*)d_in[21];
    const float* bout   = (const float*)d_in[22];
    const float* ln2g   = (const float*)d_in[23];
    const float* ln2b   = (const float*)d_in[24];
    const float* wff1   = (const float*)d_in[25];
    const float* bff1   = (const float*)d_in[26];
    const float* wff2   = (const float*)d_in[27];
    const float* bff2   = (const float*)d_in[28];
    float* out = (float*)d_out;

    float *h, *G, *sq, *ut, *umax, *umin, *psum, *psq, *mean, *rstd;
    float *y5, *t, *ln, *qkv, *z, *ff;
    int* knn;
    cudaGetSymbolAddress((void**)&h, g_h);
    cudaGetSymbolAddress((void**)&G, g_G);
    cudaGetSymbolAddress((void**)&sq, g_sq);
    cudaGetSymbolAddress((void**)&knn, g_knn);
    cudaGetSymbolAddress((void**)&ut, g_ut);
    cudaGetSymbolAddress((void**)&umax, g_umax);
    cudaGetSymbolAddress((void**)&umin, g_umin);
    cudaGetSymbolAddress((void**)&psum, g_psum);
    cudaGetSymbolAddress((void**)&psq, g_psq);
    cudaGetSymbolAddress((void**)&mean, g_mean);
    cudaGetSymbolAddress((void**)&rstd, g_rstd);
    cudaGetSymbolAddress((void**)&y5, g_y5);
    cudaGetSymbolAddress((void**)&t, g_t);
    cudaGetSymbolAddress((void**)&ln, g_ln);
    cudaGetSymbolAddress((void**)&qkv, g_qkv);
    cudaGetSymbolAddress((void**)&z, g_z);
    cudaGetSymbolAddress((void**)&ff, g_ff);

    // ---- DGCNN backbone (factorized EdgeConv, fused u/t2) ----
    edge_layer(x,       3,   3,   w1, g1, b1, 64,  0,   true,  x,
               h, G, sq, knn, ut, umax, umin, psum, psq, mean, rstd);
    edge_layer(h + 0,   512, 64,  w2, g2, b2, 64,  64,  false, nullptr,
               h, G, sq, knn, ut, umax, umin, psum, psq, mean, rstd);
    edge_layer(h + 64,  512, 64,  w3, g3, b3, 128, 128, false, nullptr,
               h, G, sq, knn, ut, umax, umin, psum, psq, mean, rstd);
    edge_layer(h + 128, 512, 128, w4, g4, b4, 256, 256, false, nullptr,
               h, G, sq, knn, ut, umax, umin, psum, psq, mean, rstd);

    // ---- conv5 ----
    {
        dim3 gg(DD / 128, NPTS / 128);
        gemm128<true, 0, false><<<gg, 256>>>(
            h, 512, 0, w5, 512, 0, nullptr, y5, DD, 0, NPTS, DD, 512);
        bn5_partial<<<NPTS / 256, 256>>>(y5, psum, psq);
        bn_reduce2<<<(DD + 255) / 256, 256>>>(psum, psq, NPTS / 256, DD, DD,
                                              1.f / (8.f * 2048.f), mean, rstd);
        pool_kernel<<<TOK, 256>>>(y5, mean, rstd, g5, b5, cls, t);
    }

    // ---- transformer ----
    for (int i = 0; i < 6; i++) {
        const float* wqkv_i = wqkv + (size_t)i * DD * 3 * INNER;
        const float* wout_i = wout + (size_t)i * INNER * DD;
        const float* bout_i = bout + (size_t)i * DD;
        const float* wff1_i = wff1 + (size_t)i * DD * MLPD;
        const float* bff1_i = bff1 + (size_t)i * MLPD;
        const float* wff2_i = wff2 + (size_t)i * MLPD * DD;
        const float* bff2_i = bff2 + (size_t)i * DD;

        ln_kernel<<<TOK, 256>>>(t, pos, ln1g + i * DD, ln1b + i * DD, ln);

        dim3 gq(3 * INNER / 64, (TOK + 63) / 64);
        gemm64<0, false><<<gq, 256>>>(ln, DD, wqkv_i, 3 * INNER, nullptr,
                                      qkv, 3 * INNER, TOK, 3 * INNER, DD);

        attn_kernel<<<dim3(65, 8, BB), 128>>>(qkv, z);

        dim3 gp(DD / 64, (TOK + 63) / 64);
        gemm64<0, true><<<gp, 256>>>(z, INNER, wout_i, DD, bout_i,
                                     t, DD, TOK, DD, INNER);

        ln_kernel<<<TOK, 256>>>(t, nullptr, ln2g + i * DD, ln2b + i * DD, ln);

        dim3 gf1(MLPD / 64, (TOK + 63) / 64);
        gemm64<1, false><<<gf1, 256>>>(ln, DD, wff1_i, MLPD, bff1_i,
                                       ff, MLPD, TOK, MLPD, DD);

        dim3 gf2(DD / 64, (TOK + 63) / 64);
        gemm64<0, true><<<gf2, 256>>>(ff, MLPD, wff2_i, DD, bff2_i,
                                      t, DD, TOK, DD, MLPD);
    }

    out_copy<<<(BB * PP * DD + 255) / 256, 256>>>(t, out);
}

// round 16
// speedup vs baseline: 1.1859x; 1.1137x over previous
#include <cuda_runtime.h>
#include <cuda_bf16.h>
#include <cfloat>
#include <math.h>

// ---------------- problem constants ----------------
#define BB 8
#define NN 2048
#define KK 20
#define PP 64
#define PS 32
#define DD 1024
#define TOK (BB * (PP + 1))   // 520
#define INNER 512
#define MLPD 2048
#define EROWS (BB * NN * KK)  // 327680
#define NPTS (BB * NN)        // 16384
#define ECPT 8                // points per stats block

// ---------------- scratch ----------------
__device__ float g_h[NPTS * 512];
__device__ float g_G[BB * NN * NN];
__device__ float g_sq[NPTS];
__device__ int   g_knn[EROWS];
__device__ float g_ut[NPTS * 512];      // interleaved u/t2: [p][2o]=u, [p][2o+1]=t2
__device__ float g_umax[NPTS * 256];
__device__ float g_umin[NPTS * 256];
__device__ float g_psum[2048 * 256];
__device__ float g_psq[2048 * 256];
__device__ float g_mean[1024];
__device__ float g_rstd[1024];
__device__ float g_y5[NPTS * DD];
__device__ float g_t[TOK * DD];
__device__ float g_ln[TOK * DD];
__device__ float g_qkv[TOK * 3 * INNER];
__device__ float g_z[TOK * INNER];
__device__ float g_ff[TOK * MLPD];

__device__ __forceinline__ float4 ld4(const float* p) { return *(const float4*)p; }

// ================= double-buffered 128x128x16 SGEMM (gram / conv5 / uv) =================
template <bool TRANSB, int ACT, bool ADDC>
__global__ __launch_bounds__(256, 2)
void gemm128(const float* __restrict__ A, int lda, size_t strideA,
             const float* __restrict__ Bm, int ldb, size_t strideB,
             const float* __restrict__ bias,
             float* __restrict__ C, int ldc, size_t strideC,
             int M, int N, int K)
{
    const int BK = 16;
    __shared__ float As[2][BK][128];
    __shared__ float Bs[2][BK][128];
    A  += (size_t)blockIdx.z * strideA;
    Bm += (size_t)blockIdx.z * strideB;
    C  += (size_t)blockIdx.z * strideC;
    int bm = blockIdx.y * 128, bn = blockIdx.x * 128;
    int tid = threadIdx.x;
    int trow = tid >> 4, tcol = tid & 15;

    float4 ra[2], rb[2];

    auto loadA = [&](int k0) {
#pragma unroll
        for (int i = 0; i < 2; i++) {
            int row = i * 64 + (tid >> 2), q = tid & 3;
            int gm = bm + row, gk = k0 + q * 4;
            if (k0 + BK <= K) {
                ra[i] = (gm < M) ? ld4(&A[(size_t)gm * lda + gk]) : make_float4(0, 0, 0, 0);
            } else {
                float v[4];
#pragma unroll
                for (int j = 0; j < 4; j++)
                    v[j] = (gm < M && gk + j < K) ? A[(size_t)gm * lda + gk + j] : 0.f;
                ra[i] = make_float4(v[0], v[1], v[2], v[3]);
            }
        }
    };
    auto loadB = [&](int k0) {
#pragma unroll
        for (int i = 0; i < 2; i++) {
            if (TRANSB) {
                int row = i * 64 + (tid >> 2), q = tid & 3;
                int gn = bn + row, gk = k0 + q * 4;
                if (k0 + BK <= K) {
                    rb[i] = (gn < N) ? ld4(&Bm[(size_t)gn * ldb + gk]) : make_float4(0, 0, 0, 0);
                } else {
                    float v[4];
#pragma unroll
                    for (int j = 0; j < 4; j++)
                        v[j] = (gn < N && gk + j < K) ? Bm[(size_t)gn * ldb + gk + j] : 0.f;
                    rb[i] = make_float4(v[0], v[1], v[2], v[3]);
                }
            } else {
                int krow = i * 8 + (tid >> 5), nq = tid & 31;
                int gk = k0 + krow, gn = bn + nq * 4;
                if (gk < K && gn < N) rb[i] = ld4(&Bm[(size_t)gk * ldb + gn]);
                else rb[i] = make_float4(0, 0, 0, 0);
            }
        }
    };
    auto storeA = [&](int p) {
#pragma unroll
        for (int i = 0; i < 2; i++) {
            int row = i * 64 + (tid >> 2), q = tid & 3;
            As[p][q * 4 + 0][row] = ra[i].x;
            As[p][q * 4 + 1][row] = ra[i].y;
            As[p][q * 4 + 2][row] = ra[i].z;
            As[p][q * 4 + 3][row] = ra[i].w;
        }
    };
    auto storeB = [&](int p) {
#pragma unroll
        for (int i = 0; i < 2; i++) {
            if (TRANSB) {
                int row = i * 64 + (tid >> 2), q = tid & 3;
                Bs[p][q * 4 + 0][row] = rb[i].x;
                Bs[p][q * 4 + 1][row] = rb[i].y;
                Bs[p][q * 4 + 2][row] = rb[i].z;
                Bs[p][q * 4 + 3][row] = rb[i].w;
            } else {
                int krow = i * 8 + (tid >> 5), nq = tid & 31;
                *(float4*)&Bs[p][krow][nq * 4] = rb[i];
            }
        }
    };

    float acc[8][8];
#pragma unroll
    for (int i = 0; i < 8; i++)
#pragma unroll
        for (int j = 0; j < 8; j++) acc[i][j] = 0.f;

    int nk = (K + BK - 1) / BK;
    loadA(0); loadB(0);
    storeA(0); storeB(0);
    __syncthreads();
    int p = 0;
    for (int it = 0; it < nk; it++) {
        if (it + 1 < nk) { loadA((it + 1) * BK); loadB((it + 1) * BK); }
#pragma unroll
        for (int k = 0; k < BK; k++) {
            float4 a0 = ld4(&As[p][k][trow * 8]);
            float4 a1 = ld4(&As[p][k][trow * 8 + 4]);
            float4 b0 = ld4(&Bs[p][k][tcol * 8]);
            float4 b1 = ld4(&Bs[p][k][tcol * 8 + 4]);
            float a[8] = {a0.x, a0.y, a0.z, a0.w, a1.x, a1.y, a1.z, a1.w};
            float b[8] = {b0.x, b0.y, b0.z, b0.w, b1.x, b1.y, b1.z, b1.w};
#pragma unroll
            for (int i = 0; i < 8; i++)
#pragma unroll
                for (int j = 0; j < 8; j++) acc[i][j] += a[i] * b[j];
        }
        if (it + 1 < nk) { storeA(p ^ 1); storeB(p ^ 1); }
        __syncthreads();
        p ^= 1;
    }
#pragma unroll
    for (int i = 0; i < 8; i++) {
        int gm = bm + trow * 8 + i;
        if (gm >= M) continue;
#pragma unroll
        for (int j = 0; j < 8; j++) {
            int gn = bn + tcol * 8 + j;
            if (gn >= N) continue;
            float v = acc[i][j];
            if (bias) v += bias[gn];
            if (ACT == 1) v = 0.5f * v * (1.f + erff(v * 0.70710678118654752f));
            size_t off = (size_t)gm * ldc + gn;
            if (ADDC) v += C[off];
            C[off] = v;
        }
    }
}

// ================= double-buffered 64x64x32 SGEMM (transformer, B=[K,N]) =================
template <int ACT, bool ADDC>
__global__ __launch_bounds__(256)
void gemm64(const float* __restrict__ A, int lda,
            const float* __restrict__ Bm, int ldb,
            const float* __restrict__ bias,
            float* __restrict__ C, int ldc,
            int M, int N, int K)
{
    const int BK = 32;
    __shared__ float As[2][BK][64];
    __shared__ float Bs[2][BK][64];
    int bm = blockIdx.y * 64, bn = blockIdx.x * 64;
    int tid = threadIdx.x;
    int trow = tid >> 4, tcol = tid & 15;
    float4 ra[2], rb[2];

    auto loadA = [&](int k0) {
        int row = tid >> 2, q = tid & 3;
        int gm = bm + row, gk = k0 + q * 8;
        if (gm < M) {
            ra[0] = ld4(&A[(size_t)gm * lda + gk]);
            ra[1] = ld4(&A[(size_t)gm * lda + gk + 4]);
        } else {
            ra[0] = make_float4(0, 0, 0, 0);
            ra[1] = make_float4(0, 0, 0, 0);
        }
    };
    auto loadB = [&](int k0) {
        int krow = tid >> 3, gn = bn + (tid & 7) * 8;
        int gk = k0 + krow;
        rb[0] = ld4(&Bm[(size_t)gk * ldb + gn]);
        rb[1] = ld4(&Bm[(size_t)gk * ldb + gn + 4]);
    };
    auto storeA = [&](int p) {
        int row = tid >> 2, q = tid & 3;
#pragma unroll
        for (int i = 0; i < 2; i++) {
            As[p][q * 8 + i * 4 + 0][row] = (i ? ra[1].x : ra[0].x);
            As[p][q * 8 + i * 4 + 1][row] = (i ? ra[1].y : ra[0].y);
            As[p][q * 8 + i * 4 + 2][row] = (i ? ra[1].z : ra[0].z);
            As[p][q * 8 + i * 4 + 3][row] = (i ? ra[1].w : ra[0].w);
        }
    };
    auto storeB = [&](int p) {
        int krow = tid >> 3, nq = (tid & 7) * 8;
        *(float4*)&Bs[p][krow][nq] = rb[0];
        *(float4*)&Bs[p][krow][nq + 4] = rb[1];
    };

    float acc[4][4];
#pragma unroll
    for (int i = 0; i < 4; i++)
#pragma unroll
        for (int j = 0; j < 4; j++) acc[i][j] = 0.f;

    int nk = K / BK;
    loadA(0); loadB(0);
    storeA(0); storeB(0);
    __syncthreads();
    int p = 0;
    for (int it = 0; it < nk; it++) {
        if (it + 1 < nk) { loadA((it + 1) * BK); loadB((it + 1) * BK); }
#pragma unroll
        for (int k = 0; k < BK; k++) {
            float4 a4 = ld4(&As[p][k][trow * 4]);
            float4 b4 = ld4(&Bs[p][k][tcol * 4]);
            float a[4] = {a4.x, a4.y, a4.z, a4.w};
            float b[4] = {b4.x, b4.y, b4.z, b4.w};
#pragma unroll
            for (int i = 0; i < 4; i++)
#pragma unroll
                for (int j = 0; j < 4; j++) acc[i][j] += a[i] * b[j];
        }
        if (it + 1 < nk) { storeA(p ^ 1); storeB(p ^ 1); }
        __syncthreads();
        p ^= 1;
    }
#pragma unroll
    for (int i = 0; i < 4; i++) {
        int gm = bm + trow * 4 + i;
        if (gm >= M) continue;
#pragma unroll
        for (int j = 0; j < 4; j++) {
            int gn = bn + tcol * 4 + j;
            float v = acc[i][j];
            if (bias) v += bias[gn];
            if (ACT == 1) v = 0.5f * v * (1.f + erff(v * 0.70710678118654752f));
            size_t off = (size_t)gm * ldc + gn;
            if (ADDC) v += C[off];
            C[off] = v;
        }
    }
}

// ================= EdgeConv via per-point factorization (interleaved ut) =================
__global__ void ec_uv_stats(const float* __restrict__ ut,
                            const int* __restrict__ knn, int O,
                            float* __restrict__ umax, float* __restrict__ umin,
                            float* __restrict__ psum, float* __restrict__ psq)
{
    __shared__ int sk[ECPT * KK];
    int blk = blockIdx.x;
    int o = threadIdx.x;         // O threads
    int base = blk * ECPT;
    int O2 = 2 * O;
    for (int i = o; i < ECPT * KK; i += blockDim.x) {
        int p = base + i / KK;
        sk[i] = ((p >> 11) << 11) + knn[(size_t)base * KK + i];
    }
    __syncthreads();
    float S = 0.f, Q = 0.f;
    for (int pi = 0; pi < ECPT; pi++) {
        int p = base + pi;
        float2 uv = *(const float2*)&ut[(size_t)p * O2 + 2 * o];
        float v = uv.y - uv.x;
        float mx = -FLT_MAX, mn = FLT_MAX;
#pragma unroll
        for (int k = 0; k < KK; k++) {
            float uu = ut[(size_t)sk[pi * KK + k] * O2 + 2 * o];
            mx = fmaxf(mx, uu);
            mn = fminf(mn, uu);
            float y = uu + v;
            S += y;
            Q += y * y;
        }
        umax[(size_t)p * O + o] = mx;
        umin[(size_t)p * O + o] = mn;
    }
    psum[(size_t)blk * O + o] = S;
    psq[(size_t)blk * O + o] = Q;
}

// Dense apply: BN affine + lrelu of extremal u + v. No gather.
__global__ void ec_apply_uv(const float* __restrict__ ut,
                            const float* __restrict__ umax, const float* __restrict__ umin,
                            const float* __restrict__ mean, const float* __restrict__ rstd,
                            const float* __restrict__ gam, const float* __restrict__ bet,
                            float* __restrict__ outH, int outOff, int O)
{
    int idx = blockIdx.x * blockDim.x + threadIdx.x;   // NPTS*O
    int p = idx / O, o = idx - p * O;
    float al = gam[o] * rstd[o];
    float be = bet[o] - mean[o] * al;
    float2 uv = *(const float2*)&ut[(size_t)p * 2 * O + 2 * o];
    float v = uv.y - uv.x;
    float m = (al >= 0.f) ? umax[idx] : umin[idx];
    float val = al * (m + v) + be;
    val = (val >= 0.f) ? val : 0.2f * val;
    outH[(size_t)p * 512 + outOff + o] = val;
}

// ---------------- parallel deterministic BN finalize: one block per channel ----------------
__global__ void bn_reduce_par(const float* __restrict__ psum, const float* __restrict__ psq,
                              int npart, int O, int bnsz, float cnt_inv,
                              float* __restrict__ mean, float* __restrict__ rstd)
{
    __shared__ float r1[256], r2[256];
    int o = blockIdx.x;          // channel
    int tid = threadIdx.x;       // 256
    int colblk = o / bnsz, c = o % bnsz;
    const float* ps = psum + (size_t)colblk * npart * bnsz + c;
    const float* pq = psq + (size_t)colblk * npart * bnsz + c;
    float s = 0.f, s2 = 0.f;
    for (int i = tid; i < npart; i += 256) {
        s  += ps[(size_t)i * bnsz];
        s2 += pq[(size_t)i * bnsz];
    }
    r1[tid] = s; r2[tid] = s2;
    __syncthreads();
    for (int st = 128; st > 0; st >>= 1) {
        if (tid < st) { r1[tid] += r1[tid + st]; r2[tid] += r2[tid + st]; }
        __syncthreads();
    }
    if (tid == 0) {
        float mu = r1[0] * cnt_inv;
        float var = r2[0] * cnt_inv - mu * mu;
        mean[o] = mu;
        rstd[o] = rsqrtf(var + 1e-5f);
    }
}

__global__ void diag_kernel(const float* __restrict__ G, float* __restrict__ sq)
{
    int bn = blockIdx.x * blockDim.x + threadIdx.x;
    if (bn < NPTS) {
        int b = bn >> 11, n = bn & 2047;
        sq[bn] = G[((size_t)b * NN + n) * NN + n];
    }
}

// ---------------- kNN select core (cached per-thread argmax) ----------------
#define KNN_SELECT_BODY(dist, out, bn)                                           \
    {                                                                            \
        float bv = -FLT_MAX; int bi = 0x7fffffff;                                \
        _Pragma("unroll")                                                        \
        for (int u2 = 0; u2 < NN / 256; u2++) {                                  \
            int j = u2 * 256 + tid;                                              \
            float v = dist[j];                                                   \
            if (v > bv) { bv = v; bi = j; }                                      \
        }                                                                        \
        for (int sel = 0; sel < KK; sel++) {                                     \
            float cv = bv; int ci = bi;                                          \
            _Pragma("unroll")                                                    \
            for (int off = 16; off > 0; off >>= 1) {                             \
                float ov = __shfl_down_sync(0xffffffffu, cv, off);               \
                int oi = __shfl_down_sync(0xffffffffu, ci, off);                 \
                if (ov > cv || (ov == cv && oi < ci)) { cv = ov; ci = oi; }      \
            }                                                                    \
            if (lane == 0) { wv[warp] = cv; wi[warp] = ci; }                     \
            __syncthreads();                                                     \
            if (tid == 0) {                                                      \
                float fv = wv[0]; int fi = wi[0];                                \
                _Pragma("unroll")                                                \
                for (int w = 1; w < 8; w++)                                      \
                    if (wv[w] > fv || (wv[w] == fv && wi[w] < fi)) {             \
                        fv = wv[w]; fi = wi[w];                                  \
                    }                                                            \
                out[(bn) * KK + sel] = fi;                                       \
                sfi = fi;                                                        \
            }                                                                    \
            __syncthreads();                                                     \
            int fi = sfi;                                                        \
            if ((fi & 255) == tid) {                                             \
                dist[fi] = -FLT_MAX;                                             \
                bv = -FLT_MAX; bi = 0x7fffffff;                                  \
                _Pragma("unroll")                                                \
                for (int u2 = 0; u2 < NN / 256; u2++) {                          \
                    int j = u2 * 256 + tid;                                      \
                    float v = dist[j];                                           \
                    if (v > bv) { bv = v; bi = j; }                              \
                }                                                                \
            }                                                                    \
        }                                                                        \
    }

__global__ void knn_select(const float* __restrict__ G, const float* __restrict__ sq,
                           int* __restrict__ out)
{
    int bn = blockIdx.x;
    int b = bn >> 11, n = bn & 2047;
    __shared__ float dist[NN];
    __shared__ float wv[8];
    __shared__ int wi[8];
    __shared__ int sfi;
    int tid = threadIdx.x;
    int lane = tid & 31, warp = tid >> 5;
    const float* row = G + ((size_t)b * NN + n) * NN;
    const float* sqb = sq + (b << 11);
    float sqn = sqb[n];
    for (int j = tid; j < NN; j += 256)
        dist[j] = 2.f * row[j] - sqn - sqb[j];
    __syncthreads();
    KNN_SELECT_BODY(dist, out, bn)
}

__global__ void knn_xyz(const float* __restrict__ x, int* __restrict__ out)
{
    int bn = blockIdx.x;
    int b = bn >> 11, n = bn & 2047;
    __shared__ float dist[NN];
    __shared__ float sx[NN], sy[NN], sz[NN], ssq[NN];
    __shared__ float wv[8];
    __shared__ int wi[8];
    __shared__ int sfi;
    int tid = threadIdx.x;
    int lane = tid & 31, warp = tid >> 5;
    const float* xb = x + (size_t)(b << 11) * 3;
    for (int j = tid; j < NN; j += 256) {
        float xv = xb[j * 3 + 0], yv = xb[j * 3 + 1], zv = xb[j * 3 + 2];
        sx[j] = xv; sy[j] = yv; sz[j] = zv;
        float s = 0.f;
        s = __fmaf_rn(xv, xv, s);
        s = __fmaf_rn(yv, yv, s);
        s = __fmaf_rn(zv, zv, s);
        ssq[j] = s;
    }
    __syncthreads();
    float xi = sx[n], yi = sy[n], zi = sz[n];
    float sqn = ssq[n];
    for (int j = tid; j < NN; j += 256) {
        float s = 0.f;
        s = __fmaf_rn(xi, sx[j], s);
        s = __fmaf_rn(yi, sy[j], s);
        s = __fmaf_rn(zi, sz[j], s);
        dist[j] = 2.f * s - sqn - ssq[j];
    }
    __syncthreads();
    KNN_SELECT_BODY(dist, out, bn)
}

// ---------------- conv5 BN partials ----------------
__global__ void bn5_partial(const float* __restrict__ y5, float* __restrict__ psum,
                            float* __restrict__ psq)
{
    int blk = blockIdx.x;
    int t0 = blk * 256;
    int tid = threadIdx.x;
    float s[4] = {0, 0, 0, 0}, s2[4] = {0, 0, 0, 0};
    for (int t = t0; t < t0 + 256; t++) {
        const float* row = y5 + (size_t)t * DD;
#pragma unroll
        for (int i = 0; i < 4; i++) {
            float v = row[tid + i * 256];
            s[i] += v; s2[i] += v * v;
        }
    }
#pragma unroll
    for (int i = 0; i < 4; i++) {
        psum[(size_t)blk * DD + tid + i * 256] = s[i];
        psq[(size_t)blk * DD + tid + i * 256] = s2[i];
    }
}

// ---------------- BN5 + leaky + patch max-pool + cls ----------------
__global__ void pool_kernel(const float* __restrict__ y5, const float* __restrict__ mean,
                            const float* __restrict__ rstd, const float* __restrict__ g5,
                            const float* __restrict__ b5, const float* __restrict__ cls,
                            float* __restrict__ t)
{
    int tok = blockIdx.x;
    int b = tok / 65, l = tok - b * 65;
    int tid = threadIdx.x;
    if (l == 0) {
        for (int d = tid; d < DD; d += 256) t[(size_t)tok * DD + d] = cls[d];
    } else {
        int p = l - 1;
        int base = b * NN + p * PS;
        for (int d = tid; d < DD; d += 256) {
            float mu = mean[d], rs = rstd[d], gg = g5[d], bb = b5[d];
            float m = -FLT_MAX;
            for (int s = 0; s < PS; s++) {
                float v = y5[(size_t)(base + s) * DD + d];
                v = (v - mu) * rs * gg + bb;
                v = (v >= 0.f) ? v : 0.2f * v;
                m = fmaxf(m, v);
            }
            t[(size_t)tok * DD + d] = m;
        }
    }
}

// ---------------- LayerNorm (optional fused pos-add) ----------------
__global__ void ln_kernel(float* __restrict__ t, const float* __restrict__ pos,
                          const float* __restrict__ g, const float* __restrict__ b,
                          float* __restrict__ out)
{
    int tok = blockIdx.x, tid = threadIdx.x;
    __shared__ float rs1[256], rs2[256];
    float* trow = t + (size_t)tok * DD;
    float loc[4];
    float s = 0.f, s2 = 0.f;
#pragma unroll
    for (int i = 0; i < 4; i++) {
        int d = tid + i * 256;
        float v = trow[d];
        if (pos) { v += pos[(size_t)tok * DD + d]; trow[d] = v; }
        loc[i] = v; s += v; s2 += v * v;
    }
    rs1[tid] = s; rs2[tid] = s2;
    __syncthreads();
    for (int st = 128; st > 0; st >>= 1) {
        if (tid < st) { rs1[tid] += rs1[tid + st]; rs2[tid] += rs2[tid + st]; }
        __syncthreads();
    }
    float mean = rs1[0] * (1.f / DD);
    float var = rs2[0] * (1.f / DD) - mean * mean;
    float rstd = rsqrtf(var + 1e-5f);
#pragma unroll
    for (int i = 0; i < 4; i++) {
        int d = tid + i * 256;
        out[(size_t)tok * DD + d] = (loc[i] - mean) * rstd * g[d] + b[d];
    }
}

// ---------------- attention ----------------
__global__ void attn_kernel(const float* __restrict__ qkv, float* __restrict__ z)
{
    int l = blockIdx.x, hh = blockIdx.y, b = blockIdx.z;
    int tid = threadIdx.x;   // 128
    __shared__ float sq_[64];
    __shared__ float sc[65];
    __shared__ float sinv;
    const float* qrow = qkv + (size_t)(b * 65 + l) * 1536 + hh * 64;
    if (tid < 64) sq_[tid] = qrow[tid];
    __syncthreads();
    if (tid < 65) {
        const float* krow = qkv + (size_t)(b * 65 + tid) * 1536 + 512 + hh * 64;
        float s = 0.f;
#pragma unroll 16
        for (int d = 0; d < 64; d++) s += sq_[d] * krow[d];
        sc[tid] = s * 0.125f;
    }
    __syncthreads();
    if (tid == 0) {
        float mx = -FLT_MAX;
        for (int m = 0; m < 65; m++) mx = fmaxf(mx, sc[m]);
        float sum = 0.f;
        for (int m = 0; m < 65; m++) { float e = expf(sc[m] - mx); sc[m] = e; sum += e; }
        sinv = 1.f / sum;
    }
    __syncthreads();
    if (tid < 64) {
        float inv = sinv;
        float acc = 0.f;
        for (int m = 0; m < 65; m++) {
            const float* vrow = qkv + (size_t)(b * 65 + m) * 1536 + 1024 + hh * 64;
            acc += sc[m] * vrow[tid];
        }
        z[(size_t)(b * 65 + l) * INNER + hh * 64 + tid] = acc * inv;
    }
}

__global__ void out_copy(const float* __restrict__ t, float* __restrict__ out)
{
    int i = blockIdx.x * blockDim.x + threadIdx.x;
    if (i < BB * PP * DD) {
        int d = i & (DD - 1);
        int bp = i >> 10;
        int b = bp >> 6, p = bp & 63;
        out[i] = t[((size_t)(b * 65 + 1 + p) << 10) + d];
    }
}

// ---------------- host driver ----------------
static void edge_layer(const float* featPtr, int lda, int C,
                       const float* w, const float* g, const float* b,
                       int O, int outOff, bool first, const float* xyz,
                       float* h, float* G, float* sq, int* knn,
                       float* ut, float* umax, float* umin,
                       float* psum, float* psq, float* mean, float* rstd)
{
    if (first) {
        knn_xyz<<<NPTS, 256>>>(xyz, knn);
    } else {
        dim3 gg(NN / 128, NN / 128, BB);
        gemm128<true, 0, false><<<gg, 256>>>(
            featPtr, lda, (size_t)NN * lda, featPtr, lda, (size_t)NN * lda,
            nullptr, G, NN, (size_t)NN * NN, NN, NN, C);
        diag_kernel<<<(NPTS + 255) / 256, 256>>>(G, sq);
        knn_select<<<NPTS, 256>>>(G, sq, knn);
    }
    // Fused u/t2 GEMM: view w[O,2C] as [2O, C] row-major (ldb = C)
    int O2 = 2 * O;
    dim3 gu((O2 + 127) / 128, NPTS / 128);
    gemm128<true, 0, false><<<gu, 256>>>(featPtr, lda, 0, w, C, 0, nullptr,
                                         ut, O2, 0, NPTS, O2, C);
    ec_uv_stats<<<NPTS / ECPT, O>>>(ut, knn, O, umax, umin, psum, psq);
    bn_reduce_par<<<O, 256>>>(psum, psq, NPTS / ECPT, O, O,
                              1.f / (float)EROWS, mean, rstd);
    ec_apply_uv<<<NPTS * O / 256, 256>>>(ut, umax, umin, mean, rstd, g, b,
                                         h, outOff, O);
}

extern "C" void kernel_launch(void* const* d_in, const int* in_sizes, int n_in,
                              void* d_out, int out_size)
{
    const float* x      = (const float*)d_in[0];
    const float* pos    = (const float*)d_in[1];
    const float* w1 = (const float*)d_in[2];  const float* g1 = (const float*)d_in[3];  const float* b1 = (const float*)d_in[4];
    const float* w2 = (const float*)d_in[5];  const float* g2 = (const float*)d_in[6];  const float* b2 = (const float*)d_in[7];
    const float* w3 = (const float*)d_in[8];  const float* g3 = (const float*)d_in[9];  const float* b3 = (const float*)d_in[10];
    const float* w4 = (const float*)d_in[11]; const float* g4 = (const float*)d_in[12]; const float* b4 = (const float*)d_in[13];
    const float* w5 = (const float*)d_in[14]; const float* g5 = (const float*)d_in[15]; const float* b5 = (const float*)d_in[16];
    const float* cls    = (const float*)d_in[17];
    const float* ln1g   = (const float*)d_in[18];
    const float* ln1b   = (const float*)d_in[19];
    const float* wqkv   = (const float*)d_in[20];
    const float* wout   = (const float*)d_in[21];
    const float* bout   = (const float*)d_in[22];
    const float* ln2g   = (const float*)d_in[23];
    const float* ln2b   = (const float*)d_in[24];
    const float* wff1   = (const float*)d_in[25];
    const float* bff1   = (const float*)d_in[26];
    const float* wff2   = (const float*)d_in[27];
    const float* bff2   = (const float*)d_in[28];
    float* out = (float*)d_out;

    float *h, *G, *sq, *ut, *umax, *umin, *psum, *psq, *mean, *rstd;
    float *y5, *t, *ln, *qkv, *z, *ff;
    int* knn;
    cudaGetSymbolAddress((void**)&h, g_h);
    cudaGetSymbolAddress((void**)&G, g_G);
    cudaGetSymbolAddress((void**)&sq, g_sq);
    cudaGetSymbolAddress((void**)&knn, g_knn);
    cudaGetSymbolAddress((void**)&ut, g_ut);
    cudaGetSymbolAddress((void**)&umax, g_umax);
    cudaGetSymbolAddress((void**)&umin, g_umin);
    cudaGetSymbolAddress((void**)&psum, g_psum);
    cudaGetSymbolAddress((void**)&psq, g_psq);
    cudaGetSymbolAddress((void**)&mean, g_mean);
    cudaGetSymbolAddress((void**)&rstd, g_rstd);
    cudaGetSymbolAddress((void**)&y5, g_y5);
    cudaGetSymbolAddress((void**)&t, g_t);
    cudaGetSymbolAddress((void**)&ln, g_ln);
    cudaGetSymbolAddress((void**)&qkv, g_qkv);
    cudaGetSymbolAddress((void**)&z, g_z);
    cudaGetSymbolAddress((void**)&ff, g_ff);

    // ---- DGCNN backbone (factorized EdgeConv, fused u/t2) ----
    edge_layer(x,       3,   3,   w1, g1, b1, 64,  0,   true,  x,
               h, G, sq, knn, ut, umax, umin, psum, psq, mean, rstd);
    edge_layer(h + 0,   512, 64,  w2, g2, b2, 64,  64,  false, nullptr,
               h, G, sq, knn, ut, umax, umin, psum, psq, mean, rstd);
    edge_layer(h + 64,  512, 64,  w3, g3, b3, 128, 128, false, nullptr,
               h, G, sq, knn, ut, umax, umin, psum, psq, mean, rstd);
    edge_layer(h + 128, 512, 128, w4, g4, b4, 256, 256, false, nullptr,
               h, G, sq, knn, ut, umax, umin, psum, psq, mean, rstd);

    // ---- conv5 ----
    {
        dim3 gg(DD / 128, NPTS / 128);
        gemm128<true, 0, false><<<gg, 256>>>(
            h, 512, 0, w5, 512, 0, nullptr, y5, DD, 0, NPTS, DD, 512);
        bn5_partial<<<NPTS / 256, 256>>>(y5, psum, psq);
        bn_reduce_par<<<DD, 256>>>(psum, psq, NPTS / 256, DD, DD,
                                   1.f / (8.f * 2048.f), mean, rstd);
        pool_kernel<<<TOK, 256>>>(y5, mean, rstd, g5, b5, cls, t);
    }

    // ---- transformer ----
    for (int i = 0; i < 6; i++) {
        const float* wqkv_i = wqkv + (size_t)i * DD * 3 * INNER;
        const float* wout_i = wout + (size_t)i * INNER * DD;
        const float* bout_i = bout + (size_t)i * DD;
        const float* wff1_i = wff1 + (size_t)i * DD * MLPD;
        const float* bff1_i = bff1 + (size_t)i * MLPD;
        const float* wff2_i = wff2 + (size_t)i * MLPD * DD;
        const float* bff2_i = bff2 + (size_t)i * DD;

        ln_kernel<<<TOK, 256>>>(t, pos, ln1g + i * DD, ln1b + i * DD, ln);

        dim3 gq(3 * INNER / 64, (TOK + 63) / 64);
        gemm64<0, false><<<gq, 256>>>(ln, DD, wqkv_i, 3 * INNER, nullptr,
                                      qkv, 3 * INNER, TOK, 3 * INNER, DD);

        attn_kernel<<<dim3(65, 8, BB), 128>>>(qkv, z);

        dim3 gp(DD / 64, (TOK + 63) / 64);
        gemm64<0, true><<<gp, 256>>>(z, INNER, wout_i, DD, bout_i,
                                     t, DD, TOK, DD, INNER);

        ln_kernel<<<TOK, 256>>>(t, nullptr, ln2g + i * DD, ln2b + i * DD, ln);

        dim3 gf1(MLPD / 64, (TOK + 63) / 64);
        gemm64<1, false><<<gf1, 256>>>(ln, DD, wff1_i, MLPD, bff1_i,
                                       ff, MLPD, TOK, MLPD, DD);

        dim3 gf2(DD / 64, (TOK + 63) / 64);
        gemm64<0, true><<<gf2, 256>>>(ff, MLPD, wff2_i, DD, bff2_i,
                                      t, DD, TOK, DD, MLPD);
    }

    out_copy<<<(BB * PP * DD + 255) / 256, 256>>>(t, out);
}